// round 4
// baseline (speedup 1.0000x reference)
#include <cuda_runtime.h>
#include <cstdint>

// ---------------------------------------------------------------------------
// 64 attention instances: instance i uses contiguous slab [i*65536,(i+1)*65536)
// of each projection viewed as (1024,64).
// Accuracy strategy: the mean-threshold mask amplifies score errors (each
// borderline flip costs ~1e-2 on its row). So Q-proj, K-proj and QK^T use
// EXACT fp32 ascending-k FFMA chains (bit-matching the reference GEMM).
// V-proj, PV and the output GEMM (smooth error propagation only) use the
// 3xTF32 mma.sync split path for tensor-core speed.
// ---------------------------------------------------------------------------
#define NORMF 0.04419417382415922f   // 1/sqrt(512)

static __device__ float g_Qp[8192 * 512];
static __device__ float g_Kp[8192 * 512];
static __device__ float g_Vp[8192 * 512];
static __device__ float g_AO[8192 * 512];
static __device__ float g_S[67108864];       // 64*1024*1024 scores
static __device__ float4 g_stats[65536];     // per row: mean, max, 1/Z

// Packed f32x2 FMA helpers (each component is its own ascending-k chain).
#define FMA2(d, a, b, c) \
    asm("fma.rn.f32x2 %0, %1, %2, %3;" : "=l"(d) : "l"(a), "l"(b), "l"(c))
#define PACK2(d, x) \
    asm("mov.b64 %0, {%1, %1};" : "=l"(d) : "r"(x))
#define UNPK2(lo, hi, d) \
    asm("mov.b64 {%0, %1}, %2;" : "=r"(lo), "=r"(hi) : "l"(d))

__device__ __forceinline__ float tf32r(float x) {
    uint32_t u;
    asm("cvt.rna.tf32.f32 %0, %1;" : "=r"(u) : "f"(x));
    return __uint_as_float(u);
}

#define MMA8(d, a, b)                                                          \
    asm volatile("mma.sync.aligned.m16n8k8.row.col.f32.tf32.tf32.f32 "         \
                 "{%0,%1,%2,%3}, {%4,%5,%6,%7}, {%8,%9}, {%0,%1,%2,%3};"       \
                 : "+f"((d)[0]), "+f"((d)[1]), "+f"((d)[2]), "+f"((d)[3])      \
                 : "r"((a)[0]), "r"((a)[1]), "r"((a)[2]), "r"((a)[3]),         \
                   "r"((b)[0]), "r"((b)[1]))

// ===========================================================================
// EXACT-FP32 PATH
// ===========================================================================

// ---------------------------------------------------------------------------
// proj_f32: C = A(8192x512) @ W(512x512) + bias for Q (z=0) and K (z=1).
// 128x128 tile, BK=16, 2-stage double buffer (register-staged), 256 thr,
// 8x8 per thread via packed FFMA2, ascending-k accumulation per output.
// ---------------------------------------------------------------------------
__global__ void __launch_bounds__(256, 2) proj_f32(
    const float* __restrict__ x, const float* __restrict__ y,
    const float* __restrict__ qw, const float* __restrict__ qb,
    const float* __restrict__ kw, const float* __restrict__ kb)
{
    const float* A    = blockIdx.z ? y  : x;
    const float* W    = blockIdx.z ? kw : qw;
    const float* bias = blockIdx.z ? kb : qb;
    float* C          = blockIdx.z ? g_Kp : g_Qp;

    __shared__ __align__(16) float As[2][16][132];
    __shared__ __align__(16) float Bs[2][16][128];

    const int tid = threadIdx.x;
    const int row0 = blockIdx.y * 128, col0 = blockIdx.x * 128;
    const int ty = tid >> 4, tx = tid & 15;
    const int ar = tid >> 1, ac = (tid & 1) * 8;   // A: row ar, k-cols ac..ac+7
    const int br = tid >> 4, bc = (tid & 15) * 8;  // B: k-row br, n-cols bc..bc+7

    const float* Ap = A + (size_t)(row0 + ar) * 512 + ac;
    const float* Wp = W + (size_t)br * 512 + col0 + bc;

    uint64_t acc[8][4];
#pragma unroll
    for (int i = 0; i < 8; i++)
#pragma unroll
        for (int j = 0; j < 4; j++) acc[i][j] = 0ull;

    float4 a0, a1, b0, b1;
    auto LD = [&](int k0) {
        a0 = *(const float4*)(Ap + k0);
        a1 = *(const float4*)(Ap + k0 + 4);
        b0 = *(const float4*)(Wp + (size_t)k0 * 512);
        b1 = *(const float4*)(Wp + (size_t)k0 * 512 + 4);
    };
    auto ST = [&](int s) {
        As[s][ac + 0][ar] = a0.x; As[s][ac + 1][ar] = a0.y;
        As[s][ac + 2][ar] = a0.z; As[s][ac + 3][ar] = a0.w;
        As[s][ac + 4][ar] = a1.x; As[s][ac + 5][ar] = a1.y;
        As[s][ac + 6][ar] = a1.z; As[s][ac + 7][ar] = a1.w;
        *(float4*)&Bs[s][br][bc] = b0;
        *(float4*)&Bs[s][br][bc + 4] = b1;
    };
    auto CMP = [&](int s) {
#pragma unroll
        for (int kk = 0; kk < 16; kk++) {
            float4 av0 = *(const float4*)&As[s][kk][ty * 8];
            float4 av1 = *(const float4*)&As[s][kk][ty * 8 + 4];
            ulonglong2 bv0 = *(const ulonglong2*)&Bs[s][kk][tx * 8];
            ulonglong2 bv1 = *(const ulonglong2*)&Bs[s][kk][tx * 8 + 4];
            uint64_t bp[4] = {bv0.x, bv0.y, bv1.x, bv1.y};
            float af[8] = {av0.x, av0.y, av0.z, av0.w, av1.x, av1.y, av1.z, av1.w};
#pragma unroll
            for (int i = 0; i < 8; i++) {
                uint64_t ap;
                PACK2(ap, __float_as_uint(af[i]));
#pragma unroll
                for (int j = 0; j < 4; j++) FMA2(acc[i][j], ap, bp[j], acc[i][j]);
            }
        }
    };

    LD(0);
    ST(0);
    __syncthreads();
    for (int i = 0; i < 32; i++) {
        if (i + 1 < 32) LD((i + 1) * 16);
        CMP(i & 1);
        if (i + 1 < 32) ST((i + 1) & 1);
        __syncthreads();
    }

#pragma unroll
    for (int i = 0; i < 8; i++) {
        int r = row0 + ty * 8 + i;
#pragma unroll
        for (int j = 0; j < 4; j++) {
            uint32_t lo, hi;
            UNPK2(lo, hi, acc[i][j]);
            int c = col0 + tx * 8 + j * 2;
            float2 o;
            o.x = __uint_as_float(lo) + bias[c];
            o.y = __uint_as_float(hi) + bias[c + 1];
            *(float2*)(C + (size_t)r * 512 + c) = o;
        }
    }
}

// ---------------------------------------------------------------------------
// qk_f32: S = (Q @ K^T) * NORM per instance, tile 128x128, K=64 fully
// resident in smem -> one load, ONE sync, zero inner barriers.
// ---------------------------------------------------------------------------
__global__ void __launch_bounds__(256, 2) qk_f32()
{
    extern __shared__ __align__(16) float qsm[];
    float (*Qs)[132] = (float(*)[132])qsm;              // [64][132]
    float (*Ks)[132] = (float(*)[132])(qsm + 64 * 132); // [64][132]

    const int tid = threadIdx.x;
    const int inst = blockIdx.z;
    const float* Q  = g_Qp + (size_t)inst * 65536;
    const float* Kc = g_Kp + (size_t)inst * 65536;
    float* Sout = g_S + ((size_t)inst << 20);
    const int row0 = blockIdx.y * 128, col0 = blockIdx.x * 128;
    const int ty = tid >> 4, tx = tid & 15;

    // Fill: thread covers row ar, 32 k-cols starting at ac (transposed store).
    {
        const int ar = tid >> 1, ac = (tid & 1) * 32;
        const float* Qp = Q + (size_t)(row0 + ar) * 64 + ac;
        const float* Kp = Kc + (size_t)(col0 + ar) * 64 + ac;
#pragma unroll
        for (int j = 0; j < 8; j++) {
            float4 qv = *(const float4*)(Qp + j * 4);
            float4 kv = *(const float4*)(Kp + j * 4);
            int c = ac + j * 4;
            Qs[c + 0][ar] = qv.x; Qs[c + 1][ar] = qv.y;
            Qs[c + 2][ar] = qv.z; Qs[c + 3][ar] = qv.w;
            Ks[c + 0][ar] = kv.x; Ks[c + 1][ar] = kv.y;
            Ks[c + 2][ar] = kv.z; Ks[c + 3][ar] = kv.w;
        }
    }
    __syncthreads();

    uint64_t acc[8][4];
#pragma unroll
    for (int i = 0; i < 8; i++)
#pragma unroll
        for (int j = 0; j < 4; j++) acc[i][j] = 0ull;

#pragma unroll 8
    for (int kk = 0; kk < 64; kk++) {
        float4 av0 = *(const float4*)&Qs[kk][ty * 8];
        float4 av1 = *(const float4*)&Qs[kk][ty * 8 + 4];
        ulonglong2 bv0 = *(const ulonglong2*)&Ks[kk][tx * 8];
        ulonglong2 bv1 = *(const ulonglong2*)&Ks[kk][tx * 8 + 4];
        uint64_t bp[4] = {bv0.x, bv0.y, bv1.x, bv1.y};
        float af[8] = {av0.x, av0.y, av0.z, av0.w, av1.x, av1.y, av1.z, av1.w};
#pragma unroll
        for (int i = 0; i < 8; i++) {
            uint64_t ap;
            PACK2(ap, __float_as_uint(af[i]));
#pragma unroll
            for (int j = 0; j < 4; j++) FMA2(acc[i][j], ap, bp[j], acc[i][j]);
        }
    }

#pragma unroll
    for (int i = 0; i < 8; i++) {
        size_t r = (size_t)(row0 + ty * 8 + i) * 1024;
#pragma unroll
        for (int j = 0; j < 4; j++) {
            uint32_t lo, hi;
            UNPK2(lo, hi, acc[i][j]);
            float2 o;
            o.x = __uint_as_float(lo) * NORMF;
            o.y = __uint_as_float(hi) * NORMF;
            *(float2*)(Sout + r + col0 + tx * 8 + j * 2) = o;
        }
    }
}

// ===========================================================================
// SPLIT-TF32 TENSOR PATH (smooth-error GEMMs: V-proj, PV, output)
// ===========================================================================
// Block tile 128x64x16, 256 threads, 8 warps (4m x 2n), warp tile 32x32.
// Smem holds hi/lo planes in FRAGMENT order. Stage = 24KB; 2 stages = 48KB.
template <int AM, int BT, int EM>
__device__ __forceinline__ void mm_body(
    const float* __restrict__ A, int lda,
    const float* __restrict__ B, int ldb,
    const float4* __restrict__ stats,
    const float* __restrict__ bias, float scale,
    float* __restrict__ C, int ldc, int ktot)
{
    extern __shared__ float sm[];
    const int tid = threadIdx.x;
    const int lane = tid & 31, wid = tid >> 5;
    const int wm = wid & 3, wn = wid >> 2;

    int tA[2], rA[2], cA[2];
    int tB[2], nB[2], kB[2];
    float4 st0[2], st1[2];
#pragma unroll
    for (int sl = 0; sl < 2; sl++) {
        int slot = tid + sl * 256;
        int tile = slot >> 5, ln = slot & 31;
        tA[sl] = tile; rA[sl] = ln >> 2; cA[sl] = ln & 3;
        tB[sl] = tile; nB[sl] = ln >> 2; kB[sl] = ln & 3;
        if (AM) {
            int m0 = (tile & 7) * 16 + (ln >> 2);
            st0[sl] = stats[m0];
            st1[sl] = stats[m0 + 8];
        }
    }

    float acc[2][4][4];
#pragma unroll
    for (int mt = 0; mt < 2; mt++)
#pragma unroll
        for (int nt = 0; nt < 4; nt++)
#pragma unroll
            for (int e = 0; e < 4; e++) acc[mt][nt][e] = 0.f;

    float ax[2][4];
    float bx[2][2];

    auto LDF = [&](int kb) {
#pragma unroll
        for (int sl = 0; sl < 2; sl++) {
            int tm = tA[sl] & 7, tk = tA[sl] >> 3;
            const float* p = A + (size_t)(tm * 16 + rA[sl]) * lda
                               + kb + tk * 8 + cA[sl];
            const float* q = p + 8 * (size_t)lda;
            ax[sl][0] = p[0]; ax[sl][1] = q[0];
            ax[sl][2] = p[4]; ax[sl][3] = q[4];
        }
#pragma unroll
        for (int sl = 0; sl < 2; sl++) {
            int tn = tB[sl] & 7, tk = tB[sl] >> 3;
            int n = tn * 8 + nB[sl];
            int kc = kb + tk * 8 + kB[sl];
            if (BT == 0) {
                const float* p = B + (size_t)n * ldb + kc;
                bx[sl][0] = p[0]; bx[sl][1] = p[4];
            } else {
                const float* p = B + (size_t)kc * ldb + n;
                bx[sl][0] = p[0]; bx[sl][1] = p[4 * (size_t)ldb];
            }
        }
    };

    auto STF = [&](int s) {
        float* base = sm + s * 6144;
#pragma unroll
        for (int sl = 0; sl < 2; sl++) {
            float v0 = ax[sl][0], v1 = ax[sl][1], v2 = ax[sl][2], v3 = ax[sl][3];
            if (AM) {
                v0 = (v0 > st0[sl].x) ? __expf(v0 - st0[sl].y) * st0[sl].z : 0.f;
                v2 = (v2 > st0[sl].x) ? __expf(v2 - st0[sl].y) * st0[sl].z : 0.f;
                v1 = (v1 > st1[sl].x) ? __expf(v1 - st1[sl].y) * st1[sl].z : 0.f;
                v3 = (v3 > st1[sl].x) ? __expf(v3 - st1[sl].y) * st1[sl].z : 0.f;
            }
            float4 h, l;
            h.x = tf32r(v0); l.x = tf32r(v0 - h.x);
            h.y = tf32r(v1); l.y = tf32r(v1 - h.y);
            h.z = tf32r(v2); l.z = tf32r(v2 - h.z);
            h.w = tf32r(v3); l.w = tf32r(v3 - h.w);
            int slot = tid + sl * 256;
            int off = (slot >> 5) * 128 + (slot & 31) * 4;
            *(float4*)(base + off) = h;
            *(float4*)(base + 2048 + off) = l;
        }
#pragma unroll
        for (int sl = 0; sl < 2; sl++) {
            float2 h, l;
            h.x = tf32r(bx[sl][0]); l.x = tf32r(bx[sl][0] - h.x);
            h.y = tf32r(bx[sl][1]); l.y = tf32r(bx[sl][1] - h.y);
            int slot = tid + sl * 256;
            int off = (slot >> 5) * 64 + (slot & 31) * 2;
            *(float2*)(base + 4096 + off) = h;
            *(float2*)(base + 5120 + off) = l;
        }
    };

    auto CMP = [&](int s) {
        const float* base = sm + s * 6144;
#pragma unroll
        for (int tk = 0; tk < 2; tk++) {
            uint4 ah[2], al[2];
            uint2 bh[4], bl[4];
#pragma unroll
            for (int mt = 0; mt < 2; mt++) {
                int tg = tk * 8 + wm * 2 + mt;
                ah[mt] = *(const uint4*)(base + tg * 128 + lane * 4);
                al[mt] = *(const uint4*)(base + 2048 + tg * 128 + lane * 4);
            }
#pragma unroll
            for (int nt = 0; nt < 4; nt++) {
                int tg = tk * 8 + wn * 4 + nt;
                bh[nt] = *(const uint2*)(base + 4096 + tg * 64 + lane * 2);
                bl[nt] = *(const uint2*)(base + 5120 + tg * 64 + lane * 2);
            }
#pragma unroll
            for (int mt = 0; mt < 2; mt++)
#pragma unroll
                for (int nt = 0; nt < 4; nt++) {
                    MMA8(acc[mt][nt], (&ah[mt].x), (&bh[nt].x));
                    MMA8(acc[mt][nt], (&ah[mt].x), (&bl[nt].x));
                    MMA8(acc[mt][nt], (&al[mt].x), (&bh[nt].x));
                }
        }
    };

    const int nk = ktot / 16;
    LDF(0);
    STF(0);
    __syncthreads();
    for (int i = 0; i < nk; i++) {
        if (i + 1 < nk) LDF((i + 1) * 16);
        CMP(i & 1);
        if (i + 1 < nk) STF((i + 1) & 1);
        __syncthreads();
    }

#pragma unroll
    for (int mt = 0; mt < 2; mt++)
#pragma unroll
        for (int nt = 0; nt < 4; nt++) {
            int row = wm * 32 + mt * 16 + (lane >> 2);
            int col = wn * 32 + nt * 8 + (lane & 3) * 2;
            float c0 = acc[mt][nt][0], c1 = acc[mt][nt][1];
            float c2 = acc[mt][nt][2], c3 = acc[mt][nt][3];
            if (EM == 0) {
                float b0 = bias[col], b1 = bias[col + 1];
                c0 += b0; c1 += b1; c2 += b0; c3 += b1;
            } else if (EM == 1) {
                c0 *= scale; c1 *= scale; c2 *= scale; c3 *= scale;
            }
            *(float2*)(C + (size_t)row * ldc + col) = make_float2(c0, c1);
            *(float2*)(C + (size_t)(row + 8) * ldc + col) = make_float2(c2, c3);
        }
}

__global__ void __launch_bounds__(256, 2) projv_mm(
    const float* __restrict__ y,
    const float* __restrict__ vw, const float* __restrict__ vb)
{
    int row0 = blockIdx.y * 128, col0 = blockIdx.x * 64;
    mm_body<0, 1, 0>(y + (size_t)row0 * 512, 512, vw + col0, 512, nullptr,
                     vb + col0, 1.f, g_Vp + (size_t)row0 * 512 + col0, 512, 512);
}

__global__ void __launch_bounds__(256, 2) pv_mm()
{
    int inst = blockIdx.z, row0 = blockIdx.y * 128;
    mm_body<1, 1, 2>(g_S + ((size_t)inst << 20) + (size_t)row0 * 1024, 1024,
                     g_Vp + (size_t)inst * 65536, 64,
                     g_stats + inst * 1024 + row0, nullptr, 1.f,
                     g_AO + (size_t)inst * 65536 + (size_t)row0 * 64, 64, 1024);
}

__global__ void __launch_bounds__(256, 2) out_mm(
    const float* __restrict__ ow, const float* __restrict__ ob,
    float* __restrict__ out)
{
    int row0 = blockIdx.y * 128, col0 = blockIdx.x * 64;
    mm_body<0, 1, 0>(g_AO + (size_t)row0 * 512, 512, ow + col0, 512, nullptr,
                     ob + col0, 1.f, out + (size_t)row0 * 512 + col0, 512, 512);
}

// ---------------------------------------------------------------------------
// Per-row stats: mean, max, 1/Z with Z = sum_{s>mean} exp(s-max)
// ---------------------------------------------------------------------------
__global__ void __launch_bounds__(256) stats_kernel()
{
    int row = blockIdx.x;
    const float4* s = (const float4*)(g_S + ((size_t)row << 10));
    int tid = threadIdx.x;
    float4 v = s[tid];
    float lsum = (v.x + v.y) + (v.z + v.w);
    float lmax = fmaxf(fmaxf(v.x, v.y), fmaxf(v.z, v.w));
#pragma unroll
    for (int o = 16; o; o >>= 1) {
        lsum += __shfl_xor_sync(0xffffffffu, lsum, o);
        lmax = fmaxf(lmax, __shfl_xor_sync(0xffffffffu, lmax, o));
    }
    __shared__ float ssum[8], smaxs[8], szs[8];
    int wid = tid >> 5, lid = tid & 31;
    if (!lid) { ssum[wid] = lsum; smaxs[wid] = lmax; }
    __syncthreads();
    float tsum = 0.f, tmax = -1e30f;
#pragma unroll
    for (int i = 0; i < 8; i++) {
        tsum += ssum[i];
        tmax = fmaxf(tmax, smaxs[i]);
    }
    float mean = tsum * (1.0f / 1024.0f);
    float z = 0.f;
    z += (v.x > mean) ? __expf(v.x - tmax) : 0.f;
    z += (v.y > mean) ? __expf(v.y - tmax) : 0.f;
    z += (v.z > mean) ? __expf(v.z - tmax) : 0.f;
    z += (v.w > mean) ? __expf(v.w - tmax) : 0.f;
#pragma unroll
    for (int o = 16; o; o >>= 1) z += __shfl_xor_sync(0xffffffffu, z, o);
    if (!lid) szs[wid] = z;
    __syncthreads();
    if (!tid) {
        float tz = 0.f;
#pragma unroll
        for (int i = 0; i < 8; i++) tz += szs[i];
        g_stats[row] = make_float4(mean, tmax, 1.0f / tz, 0.f);
    }
}

// ---------------------------------------------------------------------------
extern "C" void kernel_launch(void* const* d_in, const int* in_sizes, int n_in,
                              void* d_out, int out_size)
{
    const float* x  = (const float*)d_in[0];
    const float* y  = (const float*)d_in[1];
    const float* qw = (const float*)d_in[2];
    const float* qb = (const float*)d_in[3];
    const float* kw = (const float*)d_in[4];
    const float* kb = (const float*)d_in[5];
    const float* vw = (const float*)d_in[6];
    const float* vb = (const float*)d_in[7];
    const float* ow = (const float*)d_in[8];
    const float* ob = (const float*)d_in[9];
    float* out = (float*)d_out;

    const int SMB = 49152;                 // mm_body: 2 stages * 24KB
    const int SMQK = 2 * 64 * 132 * 4;     // qk_f32: 67.6KB dynamic
    cudaFuncSetAttribute(qk_f32,    cudaFuncAttributeMaxDynamicSharedMemorySize, SMQK);
    cudaFuncSetAttribute(projv_mm,  cudaFuncAttributeMaxDynamicSharedMemorySize, SMB);
    cudaFuncSetAttribute(pv_mm,     cudaFuncAttributeMaxDynamicSharedMemorySize, SMB);
    cudaFuncSetAttribute(out_mm,    cudaFuncAttributeMaxDynamicSharedMemorySize, SMB);

    proj_f32<<<dim3(4, 64, 2), 256>>>(x, y, qw, qb, kw, kb);
    projv_mm<<<dim3(8, 64, 1), 256, SMB>>>(y, vw, vb);
    qk_f32<<<dim3(8, 8, 64), 256, SMQK>>>();
    stats_kernel<<<65536, 256>>>();
    pv_mm<<<dim3(1, 8, 64), 256, SMB>>>();
    out_mm<<<dim3(8, 64, 1), 256, SMB>>>(ow, ob, out);
}

// round 5
// speedup vs baseline: 1.0484x; 1.0484x over previous
#include <cuda_runtime.h>
#include <cstdint>

// ---------------------------------------------------------------------------
// 64 attention instances: instance i uses contiguous slab [i*65536,(i+1)*65536)
// of each projection viewed as (1024,64).
// Accuracy: Q-proj, K-proj, QK^T exact fp32 ascending-k FFMA (mask-stable).
// V-proj, PV, out GEMM: 3xTF32 mma.sync split path (smooth errors only).
// Stats: qk emits per-(row,128-colblock) sum/max partials; tiny reduce kernel
// makes (mean,max); pv accumulates softmax Z inline and normalizes at the end.
// ---------------------------------------------------------------------------
#define NORMF 0.04419417382415922f   // 1/sqrt(512)

static __device__ float g_Qp[8192 * 512];
static __device__ float g_Kp[8192 * 512];
static __device__ float g_Vp[8192 * 512];
static __device__ float g_AO[8192 * 512];
static __device__ float g_S[67108864];       // 64*1024*1024 scores
static __device__ float2 g_part[65536 * 8];  // per (row, colblock): sum, max
static __device__ float2 g_stats2[65536];    // per row: mean, max

#define FMA2(d, a, b, c) \
    asm("fma.rn.f32x2 %0, %1, %2, %3;" : "=l"(d) : "l"(a), "l"(b), "l"(c))
#define PACK2(d, x) \
    asm("mov.b64 %0, {%1, %1};" : "=l"(d) : "r"(x))
#define UNPK2(lo, hi, d) \
    asm("mov.b64 {%0, %1}, %2;" : "=r"(lo), "=r"(hi) : "l"(d))

__device__ __forceinline__ float tf32r(float x) {
    uint32_t u;
    asm("cvt.rna.tf32.f32 %0, %1;" : "=r"(u) : "f"(x));
    return __uint_as_float(u);
}

#define MMA8(d, a, b)                                                          \
    asm volatile("mma.sync.aligned.m16n8k8.row.col.f32.tf32.tf32.f32 "         \
                 "{%0,%1,%2,%3}, {%4,%5,%6,%7}, {%8,%9}, {%0,%1,%2,%3};"       \
                 : "+f"((d)[0]), "+f"((d)[1]), "+f"((d)[2]), "+f"((d)[3])      \
                 : "r"((a)[0]), "r"((a)[1]), "r"((a)[2]), "r"((a)[3]),         \
                   "r"((b)[0]), "r"((b)[1]))

// ===========================================================================
// EXACT-FP32 PATH
// ===========================================================================

// proj_f32: C = A(8192x512) @ W(512x512) + bias for Q (z=0) and K (z=1).
__global__ void __launch_bounds__(256, 2) proj_f32(
    const float* __restrict__ x, const float* __restrict__ y,
    const float* __restrict__ qw, const float* __restrict__ qb,
    const float* __restrict__ kw, const float* __restrict__ kb)
{
    const float* A    = blockIdx.z ? y  : x;
    const float* W    = blockIdx.z ? kw : qw;
    const float* bias = blockIdx.z ? kb : qb;
    float* C          = blockIdx.z ? g_Kp : g_Qp;

    __shared__ __align__(16) float As[2][16][132];
    __shared__ __align__(16) float Bs[2][16][128];

    const int tid = threadIdx.x;
    const int row0 = blockIdx.y * 128, col0 = blockIdx.x * 128;
    const int ty = tid >> 4, tx = tid & 15;
    const int ar = tid >> 1, ac = (tid & 1) * 8;
    const int br = tid >> 4, bc = (tid & 15) * 8;

    const float* Ap = A + (size_t)(row0 + ar) * 512 + ac;
    const float* Wp = W + (size_t)br * 512 + col0 + bc;

    uint64_t acc[8][4];
#pragma unroll
    for (int i = 0; i < 8; i++)
#pragma unroll
        for (int j = 0; j < 4; j++) acc[i][j] = 0ull;

    float4 a0, a1, b0, b1;
    auto LD = [&](int k0) {
        a0 = *(const float4*)(Ap + k0);
        a1 = *(const float4*)(Ap + k0 + 4);
        b0 = *(const float4*)(Wp + (size_t)k0 * 512);
        b1 = *(const float4*)(Wp + (size_t)k0 * 512 + 4);
    };
    auto ST = [&](int s) {
        As[s][ac + 0][ar] = a0.x; As[s][ac + 1][ar] = a0.y;
        As[s][ac + 2][ar] = a0.z; As[s][ac + 3][ar] = a0.w;
        As[s][ac + 4][ar] = a1.x; As[s][ac + 5][ar] = a1.y;
        As[s][ac + 6][ar] = a1.z; As[s][ac + 7][ar] = a1.w;
        *(float4*)&Bs[s][br][bc] = b0;
        *(float4*)&Bs[s][br][bc + 4] = b1;
    };
    auto CMP = [&](int s) {
#pragma unroll
        for (int kk = 0; kk < 16; kk++) {
            float4 av0 = *(const float4*)&As[s][kk][ty * 8];
            float4 av1 = *(const float4*)&As[s][kk][ty * 8 + 4];
            ulonglong2 bv0 = *(const ulonglong2*)&Bs[s][kk][tx * 8];
            ulonglong2 bv1 = *(const ulonglong2*)&Bs[s][kk][tx * 8 + 4];
            uint64_t bp[4] = {bv0.x, bv0.y, bv1.x, bv1.y};
            float af[8] = {av0.x, av0.y, av0.z, av0.w, av1.x, av1.y, av1.z, av1.w};
#pragma unroll
            for (int i = 0; i < 8; i++) {
                uint64_t ap;
                PACK2(ap, __float_as_uint(af[i]));
#pragma unroll
                for (int j = 0; j < 4; j++) FMA2(acc[i][j], ap, bp[j], acc[i][j]);
            }
        }
    };

    LD(0);
    ST(0);
    __syncthreads();
    for (int i = 0; i < 32; i++) {
        if (i + 1 < 32) LD((i + 1) * 16);
        CMP(i & 1);
        if (i + 1 < 32) ST((i + 1) & 1);
        __syncthreads();
    }

#pragma unroll
    for (int i = 0; i < 8; i++) {
        int r = row0 + ty * 8 + i;
        int c = col0 + tx * 8;
        uint32_t e0, e1, e2, e3;
        float4 w0, w1;
        UNPK2(e0, e1, acc[i][0]); UNPK2(e2, e3, acc[i][1]);
        w0.x = __uint_as_float(e0) + bias[c + 0];
        w0.y = __uint_as_float(e1) + bias[c + 1];
        w0.z = __uint_as_float(e2) + bias[c + 2];
        w0.w = __uint_as_float(e3) + bias[c + 3];
        UNPK2(e0, e1, acc[i][2]); UNPK2(e2, e3, acc[i][3]);
        w1.x = __uint_as_float(e0) + bias[c + 4];
        w1.y = __uint_as_float(e1) + bias[c + 5];
        w1.z = __uint_as_float(e2) + bias[c + 6];
        w1.w = __uint_as_float(e3) + bias[c + 7];
        *(float4*)(C + (size_t)r * 512 + c) = w0;
        *(float4*)(C + (size_t)r * 512 + c + 4) = w1;
    }
}

// qk_f32: S = (Q @ K^T) * NORM, tile 128x128, K=64 resident in smem.
// Emits per-(row, colblock) (sum, max) partials for the mask stats.
__global__ void __launch_bounds__(256, 2) qk_f32()
{
    extern __shared__ __align__(16) float qsm[];
    float (*Qs)[132] = (float(*)[132])qsm;
    float (*Ks)[132] = (float(*)[132])(qsm + 64 * 132);

    const int tid = threadIdx.x;
    const int lane = tid & 31;
    const int inst = blockIdx.z;
    const float* Q  = g_Qp + (size_t)inst * 65536;
    const float* Kc = g_Kp + (size_t)inst * 65536;
    float* Sout = g_S + ((size_t)inst << 20);
    const int row0 = blockIdx.y * 128, col0 = blockIdx.x * 128;
    const int ty = tid >> 4, tx = tid & 15;

    {
        const int ar = tid >> 1, ac = (tid & 1) * 32;
        const float* Qp = Q + (size_t)(row0 + ar) * 64 + ac;
        const float* Kp = Kc + (size_t)(col0 + ar) * 64 + ac;
#pragma unroll
        for (int j = 0; j < 8; j++) {
            float4 qv = *(const float4*)(Qp + j * 4);
            float4 kv = *(const float4*)(Kp + j * 4);
            int c = ac + j * 4;
            Qs[c + 0][ar] = qv.x; Qs[c + 1][ar] = qv.y;
            Qs[c + 2][ar] = qv.z; Qs[c + 3][ar] = qv.w;
            Ks[c + 0][ar] = kv.x; Ks[c + 1][ar] = kv.y;
            Ks[c + 2][ar] = kv.z; Ks[c + 3][ar] = kv.w;
        }
    }
    __syncthreads();

    uint64_t acc[8][4];
#pragma unroll
    for (int i = 0; i < 8; i++)
#pragma unroll
        for (int j = 0; j < 4; j++) acc[i][j] = 0ull;

#pragma unroll 8
    for (int kk = 0; kk < 64; kk++) {
        float4 av0 = *(const float4*)&Qs[kk][ty * 8];
        float4 av1 = *(const float4*)&Qs[kk][ty * 8 + 4];
        ulonglong2 bv0 = *(const ulonglong2*)&Ks[kk][tx * 8];
        ulonglong2 bv1 = *(const ulonglong2*)&Ks[kk][tx * 8 + 4];
        uint64_t bp[4] = {bv0.x, bv0.y, bv1.x, bv1.y};
        float af[8] = {av0.x, av0.y, av0.z, av0.w, av1.x, av1.y, av1.z, av1.w};
#pragma unroll
        for (int i = 0; i < 8; i++) {
            uint64_t ap;
            PACK2(ap, __float_as_uint(af[i]));
#pragma unroll
            for (int j = 0; j < 4; j++) FMA2(acc[i][j], ap, bp[j], acc[i][j]);
        }
    }

#pragma unroll
    for (int i = 0; i < 8; i++) {
        size_t r = (size_t)(row0 + ty * 8 + i);
        uint32_t e0, e1, e2, e3;
        float4 w0, w1;
        UNPK2(e0, e1, acc[i][0]); UNPK2(e2, e3, acc[i][1]);
        w0.x = __uint_as_float(e0) * NORMF; w0.y = __uint_as_float(e1) * NORMF;
        w0.z = __uint_as_float(e2) * NORMF; w0.w = __uint_as_float(e3) * NORMF;
        UNPK2(e0, e1, acc[i][2]); UNPK2(e2, e3, acc[i][3]);
        w1.x = __uint_as_float(e0) * NORMF; w1.y = __uint_as_float(e1) * NORMF;
        w1.z = __uint_as_float(e2) * NORMF; w1.w = __uint_as_float(e3) * NORMF;
        *(float4*)(Sout + r * 1024 + col0 + tx * 8) = w0;
        *(float4*)(Sout + r * 1024 + col0 + tx * 8 + 4) = w1;

        // Partial stats over this thread's 8 cols, reduced across 16 tx lanes.
        float s8 = ((w0.x + w0.y) + (w0.z + w0.w)) + ((w1.x + w1.y) + (w1.z + w1.w));
        float m8 = fmaxf(fmaxf(fmaxf(w0.x, w0.y), fmaxf(w0.z, w0.w)),
                         fmaxf(fmaxf(w1.x, w1.y), fmaxf(w1.z, w1.w)));
#pragma unroll
        for (int o = 1; o < 16; o <<= 1) {
            s8 += __shfl_xor_sync(0xffffffffu, s8, o);
            m8 = fmaxf(m8, __shfl_xor_sync(0xffffffffu, m8, o));
        }
        if ((lane & 15) == 0)
            g_part[((size_t)inst * 1024 + r) * 8 + blockIdx.x] = make_float2(s8, m8);
    }
}

// Tiny reduce: 8 partials per row -> (mean, max)
__global__ void __launch_bounds__(256) reduce_stats()
{
    int row = blockIdx.x * 256 + threadIdx.x;
    const float2* p = g_part + (size_t)row * 8;
    float s = 0.f, m = -1e30f;
#pragma unroll
    for (int j = 0; j < 8; j++) {
        float2 v = p[j];
        s += v.x;
        m = fmaxf(m, v.y);
    }
    g_stats2[row] = make_float2(s * (1.0f / 1024.0f), m);
}

// ===========================================================================
// SPLIT-TF32 TENSOR PATH
// ===========================================================================

// mm_body: block 128x64x16, 256 thr, 8 warps (4m x 2n), warp tile 32x32.
// BT: 0 = B[n][k], 1 = B[k][n]. EM: 0 = +bias, 2 = none.
template <int BT, int EM>
__device__ __forceinline__ void mm_body(
    const float* __restrict__ A, int lda,
    const float* __restrict__ B, int ldb,
    const float* __restrict__ bias,
    float* __restrict__ C, int ldc, int ktot)
{
    extern __shared__ float sm[];
    const int tid = threadIdx.x;
    const int lane = tid & 31, wid = tid >> 5;
    const int wm = wid & 3, wn = wid >> 2;

    int tA[2], rA[2], cA[2];
#pragma unroll
    for (int sl = 0; sl < 2; sl++) {
        int slot = tid + sl * 256;
        tA[sl] = slot >> 5; rA[sl] = (slot & 31) >> 2; cA[sl] = slot & 3;
    }

    float acc[2][4][4];
#pragma unroll
    for (int mt = 0; mt < 2; mt++)
#pragma unroll
        for (int nt = 0; nt < 4; nt++)
#pragma unroll
            for (int e = 0; e < 4; e++) acc[mt][nt][e] = 0.f;

    float ax[2][4];
    float bx[2][2];

    auto LDF = [&](int kb) {
#pragma unroll
        for (int sl = 0; sl < 2; sl++) {
            int tm = tA[sl] & 7, tk = tA[sl] >> 3;
            const float* p = A + (size_t)(tm * 16 + rA[sl]) * lda + kb + tk * 8 + cA[sl];
            const float* q = p + 8 * (size_t)lda;
            ax[sl][0] = p[0]; ax[sl][1] = q[0];
            ax[sl][2] = p[4]; ax[sl][3] = q[4];
        }
#pragma unroll
        for (int sl = 0; sl < 2; sl++) {
            int tn = tA[sl] & 7, tk = tA[sl] >> 3;
            int n = tn * 8 + rA[sl];
            int kc = kb + tk * 8 + cA[sl];
            if (BT == 0) {
                const float* p = B + (size_t)n * ldb + kc;
                bx[sl][0] = p[0]; bx[sl][1] = p[4];
            } else {
                const float* p = B + (size_t)kc * ldb + n;
                bx[sl][0] = p[0]; bx[sl][1] = p[4 * (size_t)ldb];
            }
        }
    };

    auto STF = [&](int s) {
        float* base = sm + s * 6144;
#pragma unroll
        for (int sl = 0; sl < 2; sl++) {
            float4 h, l;
            h.x = tf32r(ax[sl][0]); l.x = tf32r(ax[sl][0] - h.x);
            h.y = tf32r(ax[sl][1]); l.y = tf32r(ax[sl][1] - h.y);
            h.z = tf32r(ax[sl][2]); l.z = tf32r(ax[sl][2] - h.z);
            h.w = tf32r(ax[sl][3]); l.w = tf32r(ax[sl][3] - h.w);
            int slot = tid + sl * 256;
            int off = (slot >> 5) * 128 + (slot & 31) * 4;
            *(float4*)(base + off) = h;
            *(float4*)(base + 2048 + off) = l;
        }
#pragma unroll
        for (int sl = 0; sl < 2; sl++) {
            float2 h, l;
            h.x = tf32r(bx[sl][0]); l.x = tf32r(bx[sl][0] - h.x);
            h.y = tf32r(bx[sl][1]); l.y = tf32r(bx[sl][1] - h.y);
            int slot = tid + sl * 256;
            int off = (slot >> 5) * 64 + (slot & 31) * 2;
            *(float2*)(base + 4096 + off) = h;
            *(float2*)(base + 5120 + off) = l;
        }
    };

    auto CMP = [&](int s) {
        const float* base = sm + s * 6144;
#pragma unroll
        for (int tk = 0; tk < 2; tk++) {
            uint4 ah[2], al[2];
            uint2 bh[4], bl[4];
#pragma unroll
            for (int mt = 0; mt < 2; mt++) {
                int tg = tk * 8 + wm * 2 + mt;
                ah[mt] = *(const uint4*)(base + tg * 128 + lane * 4);
                al[mt] = *(const uint4*)(base + 2048 + tg * 128 + lane * 4);
            }
#pragma unroll
            for (int nt = 0; nt < 4; nt++) {
                int tg = tk * 8 + wn * 4 + nt;
                bh[nt] = *(const uint2*)(base + 4096 + tg * 64 + lane * 2);
                bl[nt] = *(const uint2*)(base + 5120 + tg * 64 + lane * 2);
            }
#pragma unroll
            for (int mt = 0; mt < 2; mt++)
#pragma unroll
                for (int nt = 0; nt < 4; nt++) {
                    MMA8(acc[mt][nt], (&ah[mt].x), (&bh[nt].x));
                    MMA8(acc[mt][nt], (&ah[mt].x), (&bl[nt].x));
                    MMA8(acc[mt][nt], (&al[mt].x), (&bh[nt].x));
                }
        }
    };

    const int nk = ktot / 16;
    LDF(0);
    STF(0);
    __syncthreads();
    for (int i = 0; i < nk; i++) {
        if (i + 1 < nk) LDF((i + 1) * 16);
        CMP(i & 1);
        if (i + 1 < nk) STF((i + 1) & 1);
        __syncthreads();
    }

#pragma unroll
    for (int mt = 0; mt < 2; mt++)
#pragma unroll
        for (int nt = 0; nt < 4; nt++) {
            int row = wm * 32 + mt * 16 + (lane >> 2);
            int col = wn * 32 + nt * 8 + (lane & 3) * 2;
            float c0 = acc[mt][nt][0], c1 = acc[mt][nt][1];
            float c2 = acc[mt][nt][2], c3 = acc[mt][nt][3];
            if (EM == 0) {
                float b0 = bias[col], b1 = bias[col + 1];
                c0 += b0; c1 += b1; c2 += b0; c3 += b1;
            }
            *(float2*)(C + (size_t)row * ldc + col) = make_float2(c0, c1);
            *(float2*)(C + (size_t)(row + 8) * ldc + col) = make_float2(c2, c3);
        }
}

__global__ void __launch_bounds__(256, 2) projv_mm(
    const float* __restrict__ y,
    const float* __restrict__ vw, const float* __restrict__ vb)
{
    int row0 = blockIdx.y * 128, col0 = blockIdx.x * 64;
    mm_body<1, 0>(y + (size_t)row0 * 512, 512, vw + col0, 512,
                  vb + col0, g_Vp + (size_t)row0 * 512 + col0, 512, 512);
}

__global__ void __launch_bounds__(256, 2) out_mm(
    const float* __restrict__ ow, const float* __restrict__ ob,
    float* __restrict__ out)
{
    int row0 = blockIdx.y * 128, col0 = blockIdx.x * 64;
    mm_body<1, 0>(g_AO + (size_t)row0 * 512, 512, ow + col0, 512,
                  ob + col0, out + (size_t)row0 * 512 + col0, 512, 512);
}

// ---------------------------------------------------------------------------
// pv512: O = softmax_masked(S) @ V. 512 threads, 16 warps (4m x 4n),
// block tile 128x64x16, inline Z accumulation, epilogue 1/Z normalize.
// ---------------------------------------------------------------------------
__global__ void __launch_bounds__(512, 2) pv512()
{
    extern __shared__ float sm[];
    __shared__ float z_sm[128];
    const int tid = threadIdx.x, lane = tid & 31, wid = tid >> 5;
    const int wm = wid & 3, wn = wid >> 2;
    const int inst = blockIdx.z, row0 = blockIdx.y * 128;
    const float* A = g_S + ((size_t)inst << 20) + (size_t)row0 * 1024;
    const float* B = g_Vp + (size_t)inst * 65536;
    float* C = g_AO + (size_t)inst * 65536 + (size_t)row0 * 64;
    const float2* st = g_stats2 + inst * 1024 + row0;

    const int tile = tid >> 5;
    const int tm = tile & 7, tk = tile >> 3;
    const int rA = lane >> 2, cAi = lane & 3;
    const int m0 = tm * 16 + rA;
    const float2 s0 = st[m0];
    const float2 s1 = st[m0 + 8];

    if (tid < 128) z_sm[tid] = 0.f;

    float acc[2][2][4];
#pragma unroll
    for (int mt = 0; mt < 2; mt++)
#pragma unroll
        for (int nt = 0; nt < 2; nt++)
#pragma unroll
            for (int e = 0; e < 4; e++) acc[mt][nt][e] = 0.f;

    float z0 = 0.f, z1 = 0.f;
    float ax0, ax1, ax2, ax3, bx0, bx1;

    const float* Abase = A + (size_t)m0 * 1024 + tk * 8 + cAi;
    const int nIdx = tm * 8 + rA;                 // B column (0..63)
    const float* Bbase = B + (size_t)(tk * 8 + cAi) * 64 + nIdx;

    auto LDF = [&](int kb) {
        const float* p = Abase + kb;
        const float* q = p + 8 * 1024;
        ax0 = p[0]; ax1 = q[0]; ax2 = p[4]; ax3 = q[4];
        const float* r = Bbase + (size_t)kb * 64;
        bx0 = r[0]; bx1 = r[4 * 64];
    };
    auto STF = [&](int s) {
        float* base = sm + s * 6144;
        float p0 = (ax0 > s0.x) ? __expf(ax0 - s0.y) : 0.f;
        float p1 = (ax1 > s1.x) ? __expf(ax1 - s1.y) : 0.f;
        float p2 = (ax2 > s0.x) ? __expf(ax2 - s0.y) : 0.f;
        float p3 = (ax3 > s1.x) ? __expf(ax3 - s1.y) : 0.f;
        z0 += p0 + p2;
        z1 += p1 + p3;
        float4 h, l;
        h.x = tf32r(p0); l.x = tf32r(p0 - h.x);
        h.y = tf32r(p1); l.y = tf32r(p1 - h.y);
        h.z = tf32r(p2); l.z = tf32r(p2 - h.z);
        h.w = tf32r(p3); l.w = tf32r(p3 - h.w);
        int off = tile * 128 + lane * 4;
        *(float4*)(base + off) = h;
        *(float4*)(base + 2048 + off) = l;
        float2 hb, lb;
        hb.x = tf32r(bx0); lb.x = tf32r(bx0 - hb.x);
        hb.y = tf32r(bx1); lb.y = tf32r(bx1 - hb.y);
        int offb = tile * 64 + lane * 2;
        *(float2*)(base + 4096 + offb) = hb;
        *(float2*)(base + 5120 + offb) = lb;
    };
    auto CMP = [&](int s) {
        const float* base = sm + s * 6144;
#pragma unroll
        for (int tk2 = 0; tk2 < 2; tk2++) {
            uint4 ah[2], al[2];
            uint2 bh[2], bl[2];
#pragma unroll
            for (int mt = 0; mt < 2; mt++) {
                int tg = tk2 * 8 + wm * 2 + mt;
                ah[mt] = *(const uint4*)(base + tg * 128 + lane * 4);
                al[mt] = *(const uint4*)(base + 2048 + tg * 128 + lane * 4);
            }
#pragma unroll
            for (int nt = 0; nt < 2; nt++) {
                int tg = tk2 * 8 + wn * 2 + nt;
                bh[nt] = *(const uint2*)(base + 4096 + tg * 64 + lane * 2);
                bl[nt] = *(const uint2*)(base + 5120 + tg * 64 + lane * 2);
            }
#pragma unroll
            for (int mt = 0; mt < 2; mt++)
#pragma unroll
                for (int nt = 0; nt < 2; nt++) {
                    MMA8(acc[mt][nt], (&ah[mt].x), (&bh[nt].x));
                    MMA8(acc[mt][nt], (&ah[mt].x), (&bl[nt].x));
                    MMA8(acc[mt][nt], (&al[mt].x), (&bh[nt].x));
                }
        }
    };

    LDF(0);
    STF(0);
    __syncthreads();
    for (int i = 0; i < 64; i++) {
        if (i + 1 < 64) LDF((i + 1) * 16);
        CMP(i & 1);
        if (i + 1 < 64) STF((i + 1) & 1);
        __syncthreads();
    }

    atomicAdd(&z_sm[m0], z0);
    atomicAdd(&z_sm[m0 + 8], z1);
    __syncthreads();

#pragma unroll
    for (int mt = 0; mt < 2; mt++)
#pragma unroll
        for (int nt = 0; nt < 2; nt++) {
            int row = wm * 32 + mt * 16 + (lane >> 2);
            int col = wn * 16 + nt * 8 + (lane & 3) * 2;
            float iz0 = 1.0f / z_sm[row];
            float iz1 = 1.0f / z_sm[row + 8];
            float c0 = acc[mt][nt][0] * iz0, c1 = acc[mt][nt][1] * iz0;
            float c2 = acc[mt][nt][2] * iz1, c3 = acc[mt][nt][3] * iz1;
            *(float2*)(C + (size_t)row * 64 + col) = make_float2(c0, c1);
            *(float2*)(C + (size_t)(row + 8) * 64 + col) = make_float2(c2, c3);
        }
}

// ---------------------------------------------------------------------------
extern "C" void kernel_launch(void* const* d_in, const int* in_sizes, int n_in,
                              void* d_out, int out_size)
{
    const float* x  = (const float*)d_in[0];
    const float* y  = (const float*)d_in[1];
    const float* qw = (const float*)d_in[2];
    const float* qb = (const float*)d_in[3];
    const float* kw = (const float*)d_in[4];
    const float* kb = (const float*)d_in[5];
    const float* vw = (const float*)d_in[6];
    const float* vb = (const float*)d_in[7];
    const float* ow = (const float*)d_in[8];
    const float* ob = (const float*)d_in[9];
    float* out = (float*)d_out;

    const int SMB = 49152;                 // 2 stages * 24KB
    const int SMQK = 2 * 64 * 132 * 4;     // qk_f32: 67.6KB dynamic
    cudaFuncSetAttribute(qk_f32,   cudaFuncAttributeMaxDynamicSharedMemorySize, SMQK);
    cudaFuncSetAttribute(projv_mm, cudaFuncAttributeMaxDynamicSharedMemorySize, SMB);
    cudaFuncSetAttribute(pv512,    cudaFuncAttributeMaxDynamicSharedMemorySize, SMB);
    cudaFuncSetAttribute(out_mm,   cudaFuncAttributeMaxDynamicSharedMemorySize, SMB);

    proj_f32<<<dim3(4, 64, 2), 256>>>(x, y, qw, qb, kw, kb);
    projv_mm<<<dim3(8, 64, 1), 256, SMB>>>(y, vw, vb);
    qk_f32<<<dim3(8, 8, 64), 256, SMQK>>>();
    reduce_stats<<<256, 256>>>();
    pv512<<<dim3(1, 8, 64), 512, SMB>>>();
    out_mm<<<dim3(8, 64, 1), 256, SMB>>>(ow, ob, out);
}